// round 4
// baseline (speedup 1.0000x reference)
#include <cuda_runtime.h>

// QuantileLoss: out = mean( concat( (preds[:,:3]-target[:,:3])^2  (3N elems),
//                                   lower (N), lower (N) ) )
// lower = p3>p2 ? 1000 : (p3 > 0.95*t2 ? 0 : (p3-0.95*t2)^2)
// => out = sum_rows( mse_row + 2*lower_row ) / (5*N)
//
// Kernel 1: grid-stride over 4-row units (5 float4 preds + 3 float4 target,
//           all 16B-aligned), per-block fp32 partial -> g_block[blockIdx].
// Kernel 2: one block reduces the 2048 partials in fp64 and writes the mean.
// No atomics, no device-wide fences, no mutable state across graph replays.

#define NROWS 8388608
#define UNITS (NROWS / 4)
#define NBLOCKS 2048
#define NTHREADS 256

__device__ float g_block[NBLOCKS];

__device__ __forceinline__ float row_loss(float pc0, float pc1, float pc2, float pc3,
                                          float tc0, float tc1, float tc2) {
    float d0 = pc0 - tc0;
    float d1 = pc1 - tc1;
    float d2 = pc2 - tc2;
    float mse = fmaf(d0, d0, fmaf(d1, d1, d2 * d2));
    float q = tc2 * 0.95f;
    float d = pc3 - q;
    float lower = (pc3 > pc2) ? 1000.0f : ((pc3 > q) ? 0.0f : d * d);
    return fmaf(2.0f, lower, mse);
}

__global__ __launch_bounds__(NTHREADS)
void ql_partial_kernel(const float4* __restrict__ p4,
                       const float4* __restrict__ t4) {
    const int tid = threadIdx.x;
    const int gstride = gridDim.x * blockDim.x;

    float local = 0.0f;

    for (int u = blockIdx.x * blockDim.x + tid; u < UNITS; u += gstride) {
        const float4* pb = p4 + (size_t)u * 5;   // 4 rows of preds = 5 float4
        float4 p0 = pb[0];
        float4 p1 = pb[1];
        float4 p2 = pb[2];
        float4 p3 = pb[3];
        float4 p4v = pb[4];
        const float4* tb = t4 + (size_t)u * 3;   // 4 rows of target = 3 float4
        float4 t0 = tb[0];
        float4 t1 = tb[1];
        float4 t2 = tb[2];

        // row 0: preds {p0.x,p0.y,p0.z,p0.w}   target {t0.x,t0.y,t0.z}
        float s = row_loss(p0.x, p0.y, p0.z, p0.w, t0.x, t0.y, t0.z);
        // row 1: preds {p1.y,p1.z,p1.w,p2.x}   target {t0.w,t1.x,t1.y}
        s += row_loss(p1.y, p1.z, p1.w, p2.x, t0.w, t1.x, t1.y);
        // row 2: preds {p2.z,p2.w,p3.x,p3.y}   target {t1.z,t1.w,t2.x}
        s += row_loss(p2.z, p2.w, p3.x, p3.y, t1.z, t1.w, t2.x);
        // row 3: preds {p3.w,p4v.x,p4v.y,p4v.z} target {t2.y,t2.z,t2.w}
        s += row_loss(p3.w, p4v.x, p4v.y, p4v.z, t2.y, t2.z, t2.w);

        local += s;
    }

    // warp reduce (fp32; per-thread magnitude ~1e2-1e5; final check in fp64)
    #pragma unroll
    for (int off = 16; off > 0; off >>= 1)
        local += __shfl_down_sync(0xFFFFFFFFu, local, off);

    __shared__ float warp_sums[NTHREADS / 32];
    const int warp = tid >> 5;
    const int lane = tid & 31;
    if (lane == 0) warp_sums[warp] = local;
    __syncthreads();

    if (tid == 0) {
        float bsum = 0.0f;
        #pragma unroll
        for (int w = 0; w < NTHREADS / 32; w++) bsum += warp_sums[w];
        g_block[blockIdx.x] = bsum;
    }
}

__global__ __launch_bounds__(NTHREADS)
void ql_final_kernel(float* __restrict__ out) {
    const int tid = threadIdx.x;

    double local = 0.0;
    #pragma unroll
    for (int i = tid; i < NBLOCKS; i += NTHREADS)
        local += (double)g_block[i];

    // warp reduce in fp64
    #pragma unroll
    for (int off = 16; off > 0; off >>= 1)
        local += __shfl_down_sync(0xFFFFFFFFu, local, off);

    __shared__ double warp_sums[NTHREADS / 32];
    const int warp = tid >> 5;
    const int lane = tid & 31;
    if (lane == 0) warp_sums[warp] = local;
    __syncthreads();

    if (tid == 0) {
        double total = 0.0;
        #pragma unroll
        for (int w = 0; w < NTHREADS / 32; w++) total += warp_sums[w];
        out[0] = (float)(total / (5.0 * (double)NROWS));
    }
}

extern "C" void kernel_launch(void* const* d_in, const int* in_sizes, int n_in,
                              void* d_out, int out_size) {
    const float4* preds  = (const float4*)d_in[0];   // (N,5) f32, 20B rows, base 16B-aligned
    const float4* target = (const float4*)d_in[1];   // (N,3) f32
    float* out = (float*)d_out;
    (void)in_sizes; (void)n_in; (void)out_size;

    ql_partial_kernel<<<NBLOCKS, NTHREADS>>>(preds, target);
    ql_final_kernel<<<1, NTHREADS>>>(out);
}